// round 11
// baseline (speedup 1.0000x reference)
#include <cuda_runtime.h>
#include <stdint.h>

#define NB    16
#define CCH   7
#define FCH   128
#define CW    64
#define FW    256
#define NPTS  1024
#define NIMP  768
#define NCOV  256
#define NOVER 7168
#define HID   256
#define FEATC 135

typedef unsigned long long ull;

// ───────────────────────── helpers ─────────────────────────

__device__ __forceinline__ ull fma2(ull a, ull b, ull c) {
    ull d;
    asm("fma.rn.f32x2 %0, %1, %2, %3;" : "=l"(d) : "l"(a), "l"(b), "l"(c));
    return d;
}
__device__ __forceinline__ ull pack2(float lo, float hi) {
    ull d;
    asm("mov.b64 %0, {%1, %2};" : "=l"(d) : "f"(lo), "f"(hi));
    return d;
}
__device__ __forceinline__ void unpack2(ull v, float& lo, float& hi) {
    asm("mov.b64 {%0, %1}, %2;" : "=f"(lo), "=f"(hi) : "l"(v));
}
__device__ __forceinline__ void cp_async16(void* dst, const void* src) {
    unsigned d = (unsigned)__cvta_generic_to_shared(dst);
    asm volatile("cp.async.ca.shared.global [%0], [%1], 16;\n" :: "r"(d), "l"(src));
}
#define CP_COMMIT() asm volatile("cp.async.commit_group;\n" ::: "memory")
#define CP_WAIT0()  asm volatile("cp.async.wait_group 0;\n" ::: "memory")

struct BL {
    int   i00, i01, i10, i11;
    float m00, m01, m10, m11;
    float wx, wy;
};

// Replicates the reference's point_sample coordinate math with explicit
// rounding (no FMA contraction) so the top-k selection is bit-stable.
__device__ __forceinline__ void bl_setup(float px, float py, int W, BL& o) {
    float gx = __fsub_rn(__fmul_rn(2.0f, px), 1.0f);
    float gy = __fsub_rn(__fmul_rn(2.0f, py), 1.0f);
    float x  = __fmul_rn(__fsub_rn(__fmul_rn(__fadd_rn(gx, 1.0f), (float)W), 1.0f), 0.5f);
    float y  = __fmul_rn(__fsub_rn(__fmul_rn(__fadd_rn(gy, 1.0f), (float)W), 1.0f), 0.5f);
    float x0f = floorf(x), y0f = floorf(y);
    o.wx = __fsub_rn(x, x0f);
    o.wy = __fsub_rn(y, y0f);
    float x1f = __fadd_rn(x0f, 1.0f), y1f = __fadd_rn(y0f, 1.0f);
    float wm1 = (float)(W - 1);
    bool vx0 = (x0f >= 0.0f) && (x0f <= wm1);
    bool vx1 = (x1f >= 0.0f) && (x1f <= wm1);
    bool vy0 = (y0f >= 0.0f) && (y0f <= wm1);
    bool vy1 = (y1f >= 0.0f) && (y1f <= wm1);
    int ix0 = min(max((int)x0f, 0), W - 1);
    int ix1 = min(max((int)x1f, 0), W - 1);
    int iy0 = min(max((int)y0f, 0), W - 1);
    int iy1 = min(max((int)y1f, 0), W - 1);
    o.i00 = iy0 * W + ix0; o.i01 = iy0 * W + ix1;
    o.i10 = iy1 * W + ix0; o.i11 = iy1 * W + ix1;
    o.m00 = (vx0 && vy0) ? 1.0f : 0.0f;
    o.m01 = (vx1 && vy0) ? 1.0f : 0.0f;
    o.m10 = (vx0 && vy1) ? 1.0f : 0.0f;
    o.m11 = (vx1 && vy1) ? 1.0f : 0.0f;
}

__device__ __forceinline__ float bl_sample(const float* __restrict__ plane, const BL& o) {
    float v00 = __fmul_rn(plane[o.i00], o.m00);
    float v01 = __fmul_rn(plane[o.i01], o.m01);
    float v10 = __fmul_rn(plane[o.i10], o.m10);
    float v11 = __fmul_rn(plane[o.i11], o.m11);
    float owx = __fsub_rn(1.0f, o.wx), owy = __fsub_rn(1.0f, o.wy);
    float t0 = __fmul_rn(__fmul_rn(v00, owx),  owy);
    float t1 = __fmul_rn(__fmul_rn(v01, o.wx), owy);
    float t2 = __fmul_rn(__fmul_rn(v10, owx),  o.wy);
    float t3 = __fmul_rn(__fmul_rn(v11, o.wx), o.wy);
    return __fadd_rn(__fadd_rn(__fadd_rn(t0, t1), t2), t3);
}

// ───────────────────────── k_prep ─────────────────────────
// One block per batch. top2 -> smem, keys -> smem, early-exit radix select,
// hybrid smem/shfl bitonic sort of <=1024 survivors, emit points.
#define PR_ST2   0
#define PR_KEYS  32768
#define PR_CAND  90112
#define PR_BUF   147456
#define PR_HIST  155648
#define PR_SCAN  156672
#define PR_CTRL  156800
#define PR_SMEM  156832

__global__ void __launch_bounds__(1024) k_prep(const float* __restrict__ coarse,
                                               const float* __restrict__ over_gen,
                                               const float* __restrict__ coverage,
                                               float* __restrict__ pts_out) {
    extern __shared__ char smraw[];
    float*    st2  = (float*)(smraw + PR_ST2);
    ull*      keys = (ull*)(smraw + PR_KEYS);
    ull*      cand = (ull*)(smraw + PR_CAND);
    ull*      buf  = (ull*)(smraw + PR_BUF);
    unsigned* hist = (unsigned*)(smraw + PR_HIST);
    unsigned* wsum = (unsigned*)(smraw + PR_SCAN);   // 8 warp sums
    int*      s_sel  = (int*)(smraw + PR_CTRL);
    int*      s_rank = (int*)(smraw + PR_CTRL + 4);
    int*      s_wcnt = (int*)(smraw + PR_CTRL + 8);
    int*      s_ccnt = (int*)(smraw + PR_CTRL + 12);

    int b = blockIdx.x;
    int t = threadIdx.x;

    // top-2 over 7 channels, into smem
    const float* cb = coarse + (size_t)b * CCH * 4096;
    for (int pix = t; pix < 4096; pix += 1024) {
        float m1 = __int_as_float(0xff800000), m2 = m1;
#pragma unroll
        for (int c = 0; c < CCH; c++) {
            float v = cb[c * 4096 + pix];
            if (v > m1) { m2 = m1; m1 = v; }
            else if (v > m2) { m2 = v; }
        }
        st2[pix]        = m1;
        st2[4096 + pix] = m2;
    }
    if (t == 0) { *s_wcnt = 0; }
    __syncthreads();

    // uncertainty + composite keys (value desc via order-mapped ~bits, idx asc)
    const float2* og = (const float2*)over_gen + (size_t)b * NOVER;
    for (int i = t; i < NOVER; i += 1024) {
        float2 p = og[i];
        BL o;
        bl_setup(p.x, p.y, CW, o);
        float s0 = bl_sample(st2, o);
        float s1 = bl_sample(st2 + 4096, o);
        float un = -__fsub_rn(s0, s1);
        unsigned u = __float_as_uint(un);
        u = (u & 0x80000000u) ? ~u : (u ^ 0x80000000u);
        keys[i] = ((ull)(~u) << 13) | (unsigned)i;
    }
    __syncthreads();

    // early-exit radix select
    ull* src = keys;
    ull* dstc = cand;
    int m = NOVER;
    int rank = NIMP;
    int total = 0;
    for (int byte = 5; byte >= 0; byte--) {
        int sh = byte * 8;
        if (t < 256) hist[t] = 0;
        __syncthreads();
        for (int i = t; i < m; i += 1024)
            atomicAdd(&hist[(unsigned)(src[i] >> sh) & 255u], 1u);
        __syncthreads();
        // shfl inclusive scan of the 256-bin histogram (threads 0..255)
        unsigned hv = (t < 256) ? hist[t] : 0;
        unsigned sv = hv;
#pragma unroll
        for (int off = 1; off < 32; off <<= 1) {
            unsigned n = __shfl_up_sync(0xffffffffu, sv, off);
            if ((t & 31) >= off) sv += n;
        }
        if (t < 256 && (t & 31) == 31) wsum[t >> 5] = sv;
        __syncthreads();
        if (t == 0) {
            unsigned run = 0;
#pragma unroll
            for (int w8 = 0; w8 < 8; w8++) { unsigned x = wsum[w8]; wsum[w8] = run; run += x; }
            *s_ccnt = 0;
        }
        __syncthreads();
        if (t < 256) {
            unsigned incl = sv + wsum[t >> 5];
            unsigned excl = incl - hv;
            if (excl < (unsigned)rank && (unsigned)rank <= incl) {
                *s_sel  = t;
                *s_rank = rank - (int)excl;
            }
        }
        __syncthreads();
        int sel = *s_sel;
        rank = *s_rank;
        // partition: digit<sel -> definite winner; ==sel -> candidate
        for (int i = t; i < m; i += 1024) {
            ull k = src[i];
            int d = (int)((unsigned)(k >> sh) & 255u);
            if (d < sel)       buf[atomicAdd(s_wcnt, 1)] = k;
            else if (d == sel) dstc[atomicAdd(s_ccnt, 1)] = k;
        }
        __syncthreads();
        m = *s_ccnt;
        int w = *s_wcnt;
        if (w + m <= 1024) {
            for (int i = t; i < m; i += 1024) buf[w + i] = dstc[i];
            total = w + m;
            break;
        }
        ull* tmp = src; src = dstc; dstc = tmp;
        __syncthreads();
    }
    __syncthreads();

    // hybrid bitonic sort: element in register, smem for j>=32, shfl for j<=16
    ull v = (t < total) ? buf[t] : ~0ull;
    for (unsigned k = 2; k <= 1024; k <<= 1) {
        unsigned j = k >> 1;
        for (; j >= 32; j >>= 1) {
            buf[t] = v;
            __syncthreads();
            ull c = buf[t ^ j];
            bool keepmin = (((t & k) == 0) == ((t & j) == 0));
            v = keepmin ? (v < c ? v : c) : (v < c ? c : v);
            __syncthreads();
        }
        for (; j > 0; j >>= 1) {
            ull c = __shfl_xor_sync(0xffffffffu, v, j);
            bool keepmin = (((t & k) == 0) == ((t & j) == 0));
            v = keepmin ? (v < c ? v : c) : (v < c ? c : v);
        }
    }

    float* dst = pts_out + (size_t)b * NPTS * 2;
    if (t < NIMP) {
        int n = (int)(v & 0x1FFFull);
        float2 p = og[n];
        dst[t * 2 + 0] = p.x;
        dst[t * 2 + 1] = p.y;
    } else {
        int i = t - NIMP;
        float2 p = ((const float2*)coverage)[(size_t)b * NCOV + i];
        dst[(NIMP + i) * 2 + 0] = p.x;
        dst[(NIMP + i) * 2 + 1] = p.y;
    }
}

// ───────────────────────── k_fused ─────────────────────────
// 1024 CTAs x 16 points, 256 threads. Thread tile 4pt x 4col
// (cg=t&63, pg=t>>6). Paired-x gather (LDG.64 into regs). Double-buffered
// w1 via cp.async with prefetch distance 1: the wait at the top of chunk c
// drains during compute(c-1); ONE __syncthreads per chunk. Epilogue: relu +
// w2 partials reduced by intra-warp butterfly; 224-float residual aliases cbl.
// smem floats: sfb 2*540 | w1s 2*6912 | w2s 1792 | cbl/part 384
#define FU_SFB   0
#define FU_W1S   1080
#define FU_W2S   14904
#define FU_CBL   16696
#define FU_TOT   17080   // floats -> 68320 bytes

#define CHK   27
#define SFS   20        // sfb row stride
#define NTASK (CHK * 16)

__global__ void __launch_bounds__(256, 3) k_fused(
    const float* __restrict__ fine, const float* __restrict__ coarse,
    const float* __restrict__ w1, const float* __restrict__ b1,
    const float* __restrict__ w2, const float* __restrict__ b2,
    const float* __restrict__ pts, float* __restrict__ rend)
{
    extern __shared__ float sm[];
    float*  sfb  = sm + FU_SFB;        // [2][27*20]
    float*  w1s  = sm + FU_W1S;        // [2][27*256]
    float*  w2s  = sm + FU_W2S;        // [256][7]
    int4*   fidx = (int4*)(sm + FU_CBL);          // [16] halved f2 idx
    float4* fpar = (float4*)(sm + FU_CBL + 64);   // [16] (wx, wy, xodd, sel1)
    float4* fmsk = (float4*)(sm + FU_CBL + 128);  // [16] (m00,m01,m10,m11)
    int4*   cidx = (int4*)(sm + FU_CBL + 192);
    float4* cpar = (float4*)(sm + FU_CBL + 256);
    float4* cmsk = (float4*)(sm + FU_CBL + 320);
    float*  part = sm + FU_CBL;        // reused after last cbl access (iter 3)

    int t   = threadIdx.x;
    int bp0 = blockIdx.x * 16;
    int b   = bp0 >> 10;
    int cg  = t & 63;               // col group: cols cg*4 .. cg*4+3
    int pg  = t >> 6;               // point group: pts pg*4 .. pg*4+3

    // prologue: per-point params (t<16 fine, 16<=t<32 coarse)
    if (t < 32) {
        int p_ = t & 15;
        int W  = (t < 16) ? FW : CW;
        float2 p = ((const float2*)pts)[bp0 + p_];
        BL o;
        bl_setup(p.x, p.y, W, o);
        int ix0 = o.i00 & (W - 1);
        int ix1 = o.i01 & (W - 1);
        int rb0 = o.i00 - ix0;
        int rb1 = o.i10 - ix0;
        int eb  = ix0 & ~1;
        int c2  = min(eb + 2, W - 2);
        int4  idx = make_int4((rb0 + eb) >> 1, (rb0 + c2) >> 1,
                              (rb1 + eb) >> 1, (rb1 + c2) >> 1);
        float4 par = make_float4(o.wx, o.wy, (float)(ix0 & 1),
                                 (ix1 == ix0 + 1) ? 1.0f : 0.0f);
        float4 msk = make_float4(o.m00, o.m01, o.m10, o.m11);
        if (t < 16) { fidx[p_] = idx; fpar[p_] = par; fmsk[p_] = msk; }
        else        { cidx[p_] = idx; cpar[p_] = par; cmsk[p_] = msk; }
    }
    for (int i = t; i < HID * 7; i += 256) w2s[i] = w2[i];

    // accumulators: 4 pts x 4 cols as 4x2 packed f32x2, init with bias
    ull acc2[4][2];
    {
        ull bv0 = pack2(b1[cg * 4 + 0], b1[cg * 4 + 1]);
        ull bv1 = pack2(b1[cg * 4 + 2], b1[cg * 4 + 3]);
#pragma unroll
        for (int i = 0; i < 4; i++) { acc2[i][0] = bv0; acc2[i][1] = bv1; }
    }
    __syncthreads();

    // prefetch w1 chunk 0 into buffer 0
    for (int i = t; i < CHK * 64; i += 256) {
        int kk = i >> 6, q = i & 63;
        cp_async16(&w1s[kk * 256 + q * 4], w1 + (size_t)(CCH + kk) * HID + q * 4);
    }
    CP_COMMIT();

    float2 a0[2], a1[2], b0[2], b1r[2];

    // gather chunk 0 (fine channels 0..26): issue then combine into sfb[0]
#pragma unroll
    for (int s = 0; s < 2; s++) {
        int task = s * 256 + t;
        if (task < NTASK) {
            int kk = task >> 4, p = task & 15;
            const float2* pl2 = (const float2*)(fine + ((size_t)b * FCH + kk) * 65536);
            int4 ix = fidx[p];
            float4 par = fpar[p];
            a0[s] = pl2[ix.x]; a1[s] = pl2[ix.z];
            b0[s] = make_float2(0.f, 0.f); b1r[s] = b0[s];
            if (par.z != 0.0f) { b0[s] = pl2[ix.y]; b1r[s] = pl2[ix.w]; }
        }
    }
#pragma unroll
    for (int s = 0; s < 2; s++) {
        int task = s * 256 + t;
        if (task < NTASK) {
            int kk = task >> 4, p = task & 15;
            float4 par = fpar[p];
            float4 mk  = fmsk[p];
            bool xo = par.z != 0.0f, s1 = par.w != 0.0f;
            float vx00 = xo ? a0[s].y : a0[s].x;
            float t10  = xo ? b0[s].x : a0[s].y;
            float vx10 = s1 ? t10 : vx00;
            float vx01 = xo ? a1[s].y : a1[s].x;
            float t11  = xo ? b1r[s].x : a1[s].y;
            float vx11 = s1 ? t11 : vx01;
            float owx = 1.0f - par.x, owy = 1.0f - par.y;
            sfb[kk * SFS + p] = vx00 * mk.x * (owx * owy) + vx10 * mk.y * (par.x * owy)
                              + vx01 * mk.z * (owx * par.y) + vx11 * mk.w * (par.x * par.y);
        }
    }

    for (int c = 0; c < 5; c++) {
        CP_WAIT0();        // w1 chunk c arrived (committed one iteration earlier)
        __syncthreads();   // publishes: w1buf[c&1] + sfb[c&1]; all threads past compute(c-1)

        // prefetch w1 chunk c+1 into the other buffer (safe: everyone is past
        // compute(c-1), which was the last reader of that buffer)
        if (c < 4) {
            int k1 = (c + 1) * CHK;
            float* wdst = &w1s[((c + 1) & 1) * (CHK * 256)];
            for (int i = t; i < CHK * 64; i += 256) {
                int kk = i >> 6, q = i & 63;
                int row = k1 + kk;
                int srow = (row < FCH) ? (CCH + row) : (row - FCH);
                cp_async16(&wdst[kk * 256 + q * 4], w1 + (size_t)srow * HID + q * 4);
            }
            CP_COMMIT();
            // issue paired-x gather LDGs for chunk c+1
#pragma unroll
            for (int s = 0; s < 2; s++) {
                int task = s * 256 + t;
                if (task < NTASK) {
                    int kk = task >> 4, p = task & 15;
                    int ch = k1 + kk;
                    const float2* pl2;
                    int4 ix; float4 par;
                    if (ch < FCH) {
                        pl2 = (const float2*)(fine + ((size_t)b * FCH + ch) * 65536);
                        ix = fidx[p]; par = fpar[p];
                    } else {
                        pl2 = (const float2*)(coarse + ((size_t)b * CCH + (ch - FCH)) * 4096);
                        ix = cidx[p]; par = cpar[p];
                    }
                    a0[s] = pl2[ix.x]; a1[s] = pl2[ix.z];
                    b0[s] = make_float2(0.f, 0.f); b1r[s] = b0[s];
                    if (par.z != 0.0f) { b0[s] = pl2[ix.y]; b1r[s] = pl2[ix.w]; }
                }
            }
        }

        // compute chunk c: 4pt x 4col packed f32x2
        const float* sb = sfb + (c & 1) * (CHK * SFS);
        const float* wb = &w1s[(c & 1) * (CHK * 256)];
#pragma unroll 3
        for (int kk = 0; kk < CHK; kk++) {
            float4 fv = *(const float4*)&sb[kk * SFS + pg * 4];      // broadcast
            ulonglong2 w = *(const ulonglong2*)&wb[kk * 256 + cg * 4];
            ull f0 = pack2(fv.x, fv.x);
            ull f1 = pack2(fv.y, fv.y);
            ull f2v = pack2(fv.z, fv.z);
            ull f3 = pack2(fv.w, fv.w);
            acc2[0][0] = fma2(w.x, f0, acc2[0][0]);
            acc2[0][1] = fma2(w.y, f0, acc2[0][1]);
            acc2[1][0] = fma2(w.x, f1, acc2[1][0]);
            acc2[1][1] = fma2(w.y, f1, acc2[1][1]);
            acc2[2][0] = fma2(w.x, f2v, acc2[2][0]);
            acc2[2][1] = fma2(w.y, f2v, acc2[2][1]);
            acc2[3][0] = fma2(w.x, f3, acc2[3][0]);
            acc2[3][1] = fma2(w.y, f3, acc2[3][1]);
        }

        // combine + store gathered chunk c+1 into the other sfb buffer
        if (c < 4) {
            int k1 = (c + 1) * CHK;
            float* so = sfb + ((c + 1) & 1) * (CHK * SFS);
#pragma unroll
            for (int s = 0; s < 2; s++) {
                int task = s * 256 + t;
                if (task < NTASK) {
                    int kk = task >> 4, p = task & 15;
                    int ch = k1 + kk;
                    float4 par, mk;
                    if (ch < FCH) { par = fpar[p]; mk = fmsk[p]; }
                    else          { par = cpar[p]; mk = cmsk[p]; }
                    bool xo = par.z != 0.0f, s1 = par.w != 0.0f;
                    float vx00 = xo ? a0[s].y : a0[s].x;
                    float t10  = xo ? b0[s].x : a0[s].y;
                    float vx10 = s1 ? t10 : vx00;
                    float vx01 = xo ? a1[s].y : a1[s].x;
                    float t11  = xo ? b1r[s].x : a1[s].y;
                    float vx11 = s1 ? t11 : vx01;
                    float owx = 1.0f - par.x, owy = 1.0f - par.y;
                    so[kk * SFS + p] = vx00 * mk.x * (owx * owy) + vx10 * mk.y * (par.x * owy)
                                     + vx01 * mk.z * (owx * par.y) + vx11 * mk.w * (par.x * par.y);
                }
            }
        }
    }

    // epilogue: relu + w2 partials per thread, butterfly over the warp's 32 cgs
    float pr[4][7];
#pragma unroll
    for (int i = 0; i < 4; i++) {
        float h0, h1, h2, h3;
        unpack2(acc2[i][0], h0, h1);
        unpack2(acc2[i][1], h2, h3);
        h0 = fmaxf(h0, 0.0f); h1 = fmaxf(h1, 0.0f);
        h2 = fmaxf(h2, 0.0f); h3 = fmaxf(h3, 0.0f);
        const float* w20 = &w2s[(cg * 4 + 0) * 7];
        const float* w21 = w20 + 7;
        const float* w22 = w20 + 14;
        const float* w23 = w20 + 21;
#pragma unroll
        for (int k = 0; k < 7; k++)
            pr[i][k] = h0 * w20[k] + h1 * w21[k] + h2 * w22[k] + h3 * w23[k];
    }
#pragma unroll
    for (int off = 16; off > 0; off >>= 1) {
#pragma unroll
        for (int i = 0; i < 4; i++)
#pragma unroll
            for (int k = 0; k < 7; k++)
                pr[i][k] += __shfl_xor_sync(0xffffffffu, pr[i][k], off);
    }
    int wrp = t >> 5;   // warp id; warps {2w, 2w+1} share pg=w, cover cgs 0-31 / 32-63
    if ((t & 31) == 0) {
#pragma unroll
        for (int i = 0; i < 4; i++)
#pragma unroll
            for (int k = 0; k < 7; k++)
                part[((wrp & 1) * 16 + (pg * 4 + i)) * 7 + k] = pr[i][k];
    }
    __syncthreads();

    // final: add the two warp-halves + b2, write rend[b][k][p]
    if (t < 16 * 7) {
        int p = t / 7, k = t % 7;
        float s = b2[k] + part[p * 7 + k] + part[(16 + p) * 7 + k];
        rend[((size_t)b * CCH + k) * NPTS + (bp0 & 1023) + p] = s;
    }
}

extern "C" void kernel_launch(void* const* d_in, const int* in_sizes, int n_in,
                              void* d_out, int out_size) {
    (void)in_sizes; (void)n_in; (void)out_size;
    const float* fine     = (const float*)d_in[0];
    const float* coarse   = (const float*)d_in[1];
    const float* w1       = (const float*)d_in[2];
    const float* b1       = (const float*)d_in[3];
    const float* w2       = (const float*)d_in[4];
    const float* b2       = (const float*)d_in[5];
    const float* over_gen = (const float*)d_in[6];
    const float* coverage = (const float*)d_in[7];

    float* rend = (float*)d_out;                 // [16][7][1024]
    float* pts  = rend + NB * CCH * NPTS;        // [16][1024][2]

    cudaFuncSetAttribute(k_prep,  cudaFuncAttributeMaxDynamicSharedMemorySize, PR_SMEM);
    cudaFuncSetAttribute(k_fused, cudaFuncAttributeMaxDynamicSharedMemorySize, FU_TOT * 4);

    k_prep<<<NB, 1024, PR_SMEM>>>(coarse, over_gen, coverage, pts);
    k_fused<<<NB * NPTS / 16, 256, FU_TOT * 4>>>(fine, coarse, w1, b1, w2, b2, pts, rend);
}

// round 13
// speedup vs baseline: 1.2818x; 1.2818x over previous
#include <cuda_runtime.h>
#include <stdint.h>

#define NB    16
#define CCH   7
#define FCH   128
#define CW    64
#define FW    256
#define NPTS  1024
#define NIMP  768
#define NCOV  256
#define NOVER 7168
#define HID   256
#define FEATC 135

typedef unsigned long long ull;

// ───────────────────────── helpers ─────────────────────────

__device__ __forceinline__ ull fma2(ull a, ull b, ull c) {
    ull d;
    asm("fma.rn.f32x2 %0, %1, %2, %3;" : "=l"(d) : "l"(a), "l"(b), "l"(c));
    return d;
}
__device__ __forceinline__ ull pack2(float lo, float hi) {
    ull d;
    asm("mov.b64 %0, {%1, %2};" : "=l"(d) : "f"(lo), "f"(hi));
    return d;
}
__device__ __forceinline__ void unpack2(ull v, float& lo, float& hi) {
    asm("mov.b64 {%0, %1}, %2;" : "=f"(lo), "=f"(hi) : "l"(v));
}

struct BL {
    int   i00, i01, i10, i11;
    float m00, m01, m10, m11;
    float wx, wy;
};

// Replicates the reference's point_sample coordinate math with explicit
// rounding (no FMA contraction) so the top-k selection is bit-stable.
__device__ __forceinline__ void bl_setup(float px, float py, int W, BL& o) {
    float gx = __fsub_rn(__fmul_rn(2.0f, px), 1.0f);
    float gy = __fsub_rn(__fmul_rn(2.0f, py), 1.0f);
    float x  = __fmul_rn(__fsub_rn(__fmul_rn(__fadd_rn(gx, 1.0f), (float)W), 1.0f), 0.5f);
    float y  = __fmul_rn(__fsub_rn(__fmul_rn(__fadd_rn(gy, 1.0f), (float)W), 1.0f), 0.5f);
    float x0f = floorf(x), y0f = floorf(y);
    o.wx = __fsub_rn(x, x0f);
    o.wy = __fsub_rn(y, y0f);
    float x1f = __fadd_rn(x0f, 1.0f), y1f = __fadd_rn(y0f, 1.0f);
    float wm1 = (float)(W - 1);
    bool vx0 = (x0f >= 0.0f) && (x0f <= wm1);
    bool vx1 = (x1f >= 0.0f) && (x1f <= wm1);
    bool vy0 = (y0f >= 0.0f) && (y0f <= wm1);
    bool vy1 = (y1f >= 0.0f) && (y1f <= wm1);
    int ix0 = min(max((int)x0f, 0), W - 1);
    int ix1 = min(max((int)x1f, 0), W - 1);
    int iy0 = min(max((int)y0f, 0), W - 1);
    int iy1 = min(max((int)y1f, 0), W - 1);
    o.i00 = iy0 * W + ix0; o.i01 = iy0 * W + ix1;
    o.i10 = iy1 * W + ix0; o.i11 = iy1 * W + ix1;
    o.m00 = (vx0 && vy0) ? 1.0f : 0.0f;
    o.m01 = (vx1 && vy0) ? 1.0f : 0.0f;
    o.m10 = (vx0 && vy1) ? 1.0f : 0.0f;
    o.m11 = (vx1 && vy1) ? 1.0f : 0.0f;
}

__device__ __forceinline__ float bl_sample(const float* __restrict__ plane, const BL& o) {
    float v00 = __fmul_rn(plane[o.i00], o.m00);
    float v01 = __fmul_rn(plane[o.i01], o.m01);
    float v10 = __fmul_rn(plane[o.i10], o.m10);
    float v11 = __fmul_rn(plane[o.i11], o.m11);
    float owx = __fsub_rn(1.0f, o.wx), owy = __fsub_rn(1.0f, o.wy);
    float t0 = __fmul_rn(__fmul_rn(v00, owx),  owy);
    float t1 = __fmul_rn(__fmul_rn(v01, o.wx), owy);
    float t2 = __fmul_rn(__fmul_rn(v10, owx),  o.wy);
    float t3 = __fmul_rn(__fmul_rn(v11, o.wx), o.wy);
    return __fadd_rn(__fadd_rn(__fadd_rn(t0, t1), t2), t3);
}

// ───────────────────────── k_prep ─────────────────────────
// One block per batch. top2 -> smem, keys -> smem, early-exit radix select,
// hybrid smem/shfl bitonic sort of <=1024 survivors, emit points.
#define PR_ST2   0
#define PR_KEYS  32768
#define PR_CAND  90112
#define PR_BUF   147456
#define PR_HIST  155648
#define PR_SCAN  156672
#define PR_CTRL  156800
#define PR_SMEM  156832

__global__ void __launch_bounds__(1024) k_prep(const float* __restrict__ coarse,
                                               const float* __restrict__ over_gen,
                                               const float* __restrict__ coverage,
                                               float* __restrict__ pts_out) {
    extern __shared__ char smraw[];
    float*    st2  = (float*)(smraw + PR_ST2);
    ull*      keys = (ull*)(smraw + PR_KEYS);
    ull*      cand = (ull*)(smraw + PR_CAND);
    ull*      buf  = (ull*)(smraw + PR_BUF);
    unsigned* hist = (unsigned*)(smraw + PR_HIST);
    unsigned* wsum = (unsigned*)(smraw + PR_SCAN);   // 8 warp sums
    int*      s_sel  = (int*)(smraw + PR_CTRL);
    int*      s_rank = (int*)(smraw + PR_CTRL + 4);
    int*      s_wcnt = (int*)(smraw + PR_CTRL + 8);
    int*      s_ccnt = (int*)(smraw + PR_CTRL + 12);

    int b = blockIdx.x;
    int t = threadIdx.x;

    // top-2 over 7 channels, into smem
    const float* cb = coarse + (size_t)b * CCH * 4096;
    for (int pix = t; pix < 4096; pix += 1024) {
        float m1 = __int_as_float(0xff800000), m2 = m1;
#pragma unroll
        for (int c = 0; c < CCH; c++) {
            float v = cb[c * 4096 + pix];
            if (v > m1) { m2 = m1; m1 = v; }
            else if (v > m2) { m2 = v; }
        }
        st2[pix]        = m1;
        st2[4096 + pix] = m2;
    }
    if (t == 0) { *s_wcnt = 0; }
    __syncthreads();

    // uncertainty + composite keys (value desc via order-mapped ~bits, idx asc)
    const float2* og = (const float2*)over_gen + (size_t)b * NOVER;
    for (int i = t; i < NOVER; i += 1024) {
        float2 p = og[i];
        BL o;
        bl_setup(p.x, p.y, CW, o);
        float s0 = bl_sample(st2, o);
        float s1 = bl_sample(st2 + 4096, o);
        float un = -__fsub_rn(s0, s1);
        unsigned u = __float_as_uint(un);
        u = (u & 0x80000000u) ? ~u : (u ^ 0x80000000u);
        keys[i] = ((ull)(~u) << 13) | (unsigned)i;
    }
    __syncthreads();

    // early-exit radix select
    ull* src = keys;
    ull* dstc = cand;
    int m = NOVER;
    int rank = NIMP;
    int total = 0;
    for (int byte = 5; byte >= 0; byte--) {
        int sh = byte * 8;
        if (t < 256) hist[t] = 0;
        __syncthreads();
        for (int i = t; i < m; i += 1024)
            atomicAdd(&hist[(unsigned)(src[i] >> sh) & 255u], 1u);
        __syncthreads();
        // shfl inclusive scan of the 256-bin histogram (threads 0..255)
        unsigned hv = (t < 256) ? hist[t] : 0;
        unsigned sv = hv;
#pragma unroll
        for (int off = 1; off < 32; off <<= 1) {
            unsigned n = __shfl_up_sync(0xffffffffu, sv, off);
            if ((t & 31) >= off) sv += n;
        }
        if (t < 256 && (t & 31) == 31) wsum[t >> 5] = sv;
        __syncthreads();
        if (t == 0) {
            unsigned run = 0;
#pragma unroll
            for (int w8 = 0; w8 < 8; w8++) { unsigned x = wsum[w8]; wsum[w8] = run; run += x; }
            *s_ccnt = 0;
        }
        __syncthreads();
        if (t < 256) {
            unsigned incl = sv + wsum[t >> 5];
            unsigned excl = incl - hv;
            if (excl < (unsigned)rank && (unsigned)rank <= incl) {
                *s_sel  = t;
                *s_rank = rank - (int)excl;
            }
        }
        __syncthreads();
        int sel = *s_sel;
        rank = *s_rank;
        // partition: digit<sel -> definite winner; ==sel -> candidate
        for (int i = t; i < m; i += 1024) {
            ull k = src[i];
            int d = (int)((unsigned)(k >> sh) & 255u);
            if (d < sel)       buf[atomicAdd(s_wcnt, 1)] = k;
            else if (d == sel) dstc[atomicAdd(s_ccnt, 1)] = k;
        }
        __syncthreads();
        m = *s_ccnt;
        int w = *s_wcnt;
        if (w + m <= 1024) {
            for (int i = t; i < m; i += 1024) buf[w + i] = dstc[i];
            total = w + m;
            break;
        }
        ull* tmp = src; src = dstc; dstc = tmp;
        __syncthreads();
    }
    __syncthreads();

    // hybrid bitonic sort: element in register, smem for j>=32, shfl for j<=16
    ull v = (t < total) ? buf[t] : ~0ull;
    for (unsigned k = 2; k <= 1024; k <<= 1) {
        unsigned j = k >> 1;
        for (; j >= 32; j >>= 1) {
            buf[t] = v;
            __syncthreads();
            ull c = buf[t ^ j];
            bool keepmin = (((t & k) == 0) == ((t & j) == 0));
            v = keepmin ? (v < c ? v : c) : (v < c ? c : v);
            __syncthreads();
        }
        for (; j > 0; j >>= 1) {
            ull c = __shfl_xor_sync(0xffffffffu, v, j);
            bool keepmin = (((t & k) == 0) == ((t & j) == 0));
            v = keepmin ? (v < c ? v : c) : (v < c ? c : v);
        }
    }

    float* dst = pts_out + (size_t)b * NPTS * 2;
    if (t < NIMP) {
        int n = (int)(v & 0x1FFFull);
        float2 p = og[n];
        dst[t * 2 + 0] = p.x;
        dst[t * 2 + 1] = p.y;
    } else {
        int i = t - NIMP;
        float2 p = ((const float2*)coverage)[(size_t)b * NCOV + i];
        dst[(NIMP + i) * 2 + 0] = p.x;
        dst[(NIMP + i) * 2 + 1] = p.y;
    }
}

// ───────────────────────── k_fused ─────────────────────────
// 1024 CTAs x 16 points, 256 threads. Thread tile 4pt x 4col
// (cg=t&63, pg=t>>6). Paired-x gather (LDG.64 into regs). w1 is read
// DIRECTLY from global via LDG.128 in the compute loop (138 KB, L1/L2
// resident, reused across warps/CTAs) — no smem staging, no cp.async.
// Tiny smem footprint (13 KB) keeps ~190 KB of L1D for the gathers.
// One __syncthreads per chunk. Epilogue: relu + w2 partials reduced by
// intra-warp butterfly; 224-float residual aliases the point-param region.
// smem floats: sfb 2*540 | w2s 1792 | cbl/part 384
#define FU_SFB   0
#define FU_W2S   1080
#define FU_CBL   2872
#define FU_TOT   3256   // floats -> 13024 bytes

#define CHK   27
#define SFS   20        // sfb row stride
#define NTASK (CHK * 16)

__global__ void __launch_bounds__(256, 3) k_fused(
    const float* __restrict__ fine, const float* __restrict__ coarse,
    const float* __restrict__ w1, const float* __restrict__ b1,
    const float* __restrict__ w2, const float* __restrict__ b2,
    const float* __restrict__ pts, float* __restrict__ rend)
{
    extern __shared__ float sm[];
    float*  sfb  = sm + FU_SFB;        // [2][27*20]
    float*  w2s  = sm + FU_W2S;        // [256][7]
    int4*   fidx = (int4*)(sm + FU_CBL);          // [16] halved f2 idx
    float4* fpar = (float4*)(sm + FU_CBL + 64);   // [16] (wx, wy, xodd, sel1)
    float4* fmsk = (float4*)(sm + FU_CBL + 128);  // [16] (m00,m01,m10,m11)
    int4*   cidx = (int4*)(sm + FU_CBL + 192);
    float4* cpar = (float4*)(sm + FU_CBL + 256);
    float4* cmsk = (float4*)(sm + FU_CBL + 320);
    float*  part = sm + FU_CBL;        // reused after the mainloop

    int t   = threadIdx.x;
    int bp0 = blockIdx.x * 16;
    int b   = bp0 >> 10;
    int cg  = t & 63;               // col group: cols cg*4 .. cg*4+3
    int pg  = t >> 6;               // point group: pts pg*4 .. pg*4+3

    // prologue: per-point params (t<16 fine, 16<=t<32 coarse)
    if (t < 32) {
        int p_ = t & 15;
        int W  = (t < 16) ? FW : CW;
        float2 p = ((const float2*)pts)[bp0 + p_];
        BL o;
        bl_setup(p.x, p.y, W, o);
        int ix0 = o.i00 & (W - 1);
        int ix1 = o.i01 & (W - 1);
        int rb0 = o.i00 - ix0;
        int rb1 = o.i10 - ix0;
        int eb  = ix0 & ~1;
        int c2  = min(eb + 2, W - 2);
        int4  idx = make_int4((rb0 + eb) >> 1, (rb0 + c2) >> 1,
                              (rb1 + eb) >> 1, (rb1 + c2) >> 1);
        float4 par = make_float4(o.wx, o.wy, (float)(ix0 & 1),
                                 (ix1 == ix0 + 1) ? 1.0f : 0.0f);
        float4 msk = make_float4(o.m00, o.m01, o.m10, o.m11);
        if (t < 16) { fidx[p_] = idx; fpar[p_] = par; fmsk[p_] = msk; }
        else        { cidx[p_] = idx; cpar[p_] = par; cmsk[p_] = msk; }
    }
    for (int i = t; i < HID * 7; i += 256) w2s[i] = w2[i];

    // accumulators: 4 pts x 4 cols as 4x2 packed f32x2, init with bias
    ull acc2[4][2];
    {
        ull bv0 = pack2(b1[cg * 4 + 0], b1[cg * 4 + 1]);
        ull bv1 = pack2(b1[cg * 4 + 2], b1[cg * 4 + 3]);
#pragma unroll
        for (int i = 0; i < 4; i++) { acc2[i][0] = bv0; acc2[i][1] = bv1; }
    }
    __syncthreads();

    float2 a0[2], a1[2], b0[2], b1r[2];

    // gather chunk 0 (fine channels 0..26): issue then combine into sfb[0]
#pragma unroll
    for (int s = 0; s < 2; s++) {
        int task = s * 256 + t;
        if (task < NTASK) {
            int kk = task >> 4, p = task & 15;
            const float2* pl2 = (const float2*)(fine + ((size_t)b * FCH + kk) * 65536);
            int4 ix = fidx[p];
            float4 par = fpar[p];
            a0[s] = pl2[ix.x]; a1[s] = pl2[ix.z];
            b0[s] = make_float2(0.f, 0.f); b1r[s] = b0[s];
            if (par.z != 0.0f) { b0[s] = pl2[ix.y]; b1r[s] = pl2[ix.w]; }
        }
    }
#pragma unroll
    for (int s = 0; s < 2; s++) {
        int task = s * 256 + t;
        if (task < NTASK) {
            int kk = task >> 4, p = task & 15;
            float4 par = fpar[p];
            float4 mk  = fmsk[p];
            bool xo = par.z != 0.0f, s1 = par.w != 0.0f;
            float vx00 = xo ? a0[s].y : a0[s].x;
            float t10  = xo ? b0[s].x : a0[s].y;
            float vx10 = s1 ? t10 : vx00;
            float vx01 = xo ? a1[s].y : a1[s].x;
            float t11  = xo ? b1r[s].x : a1[s].y;
            float vx11 = s1 ? t11 : vx01;
            float owx = 1.0f - par.x, owy = 1.0f - par.y;
            sfb[kk * SFS + p] = vx00 * mk.x * (owx * owy) + vx10 * mk.y * (par.x * owy)
                              + vx01 * mk.z * (owx * par.y) + vx11 * mk.w * (par.x * par.y);
        }
    }

    for (int c = 0; c < 5; c++) {
        __syncthreads();   // publish sfb[c&1]; all threads past compute(c-1)

        // issue paired-x gather LDGs for chunk c+1 (long latency cover)
        if (c < 4) {
            int k1 = (c + 1) * CHK;
#pragma unroll
            for (int s = 0; s < 2; s++) {
                int task = s * 256 + t;
                if (task < NTASK) {
                    int kk = task >> 4, p = task & 15;
                    int ch = k1 + kk;
                    const float2* pl2;
                    int4 ix; float4 par;
                    if (ch < FCH) {
                        pl2 = (const float2*)(fine + ((size_t)b * FCH + ch) * 65536);
                        ix = fidx[p]; par = fpar[p];
                    } else {
                        pl2 = (const float2*)(coarse + ((size_t)b * CCH + (ch - FCH)) * 4096);
                        ix = cidx[p]; par = cpar[p];
                    }
                    a0[s] = pl2[ix.x]; a1[s] = pl2[ix.z];
                    b0[s] = make_float2(0.f, 0.f); b1r[s] = b0[s];
                    if (par.z != 0.0f) { b0[s] = pl2[ix.y]; b1r[s] = pl2[ix.w]; }
                }
            }
        }

        // compute chunk c: 4pt x 4col packed f32x2, w1 straight from global
        const float* sb = sfb + (c & 1) * (CHK * SFS);
        if (c < 4) {
            const float* wp = w1 + (size_t)(CCH + c * CHK) * HID + cg * 4;
#pragma unroll 9
            for (int kk = 0; kk < CHK; kk++) {
                float4 fv = *(const float4*)&sb[kk * SFS + pg * 4];      // broadcast
                ulonglong2 w = *(const ulonglong2*)(wp + (size_t)kk * HID);
                ull f0 = pack2(fv.x, fv.x);
                ull f1 = pack2(fv.y, fv.y);
                ull f2v = pack2(fv.z, fv.z);
                ull f3 = pack2(fv.w, fv.w);
                acc2[0][0] = fma2(w.x, f0, acc2[0][0]);
                acc2[0][1] = fma2(w.y, f0, acc2[0][1]);
                acc2[1][0] = fma2(w.x, f1, acc2[1][0]);
                acc2[1][1] = fma2(w.y, f1, acc2[1][1]);
                acc2[2][0] = fma2(w.x, f2v, acc2[2][0]);
                acc2[2][1] = fma2(w.y, f2v, acc2[2][1]);
                acc2[3][0] = fma2(w.x, f3, acc2[3][0]);
                acc2[3][1] = fma2(w.y, f3, acc2[3][1]);
            }
        } else {
            // chunk 4: rows 108..134 -> srow 115..134 (fine), then 0..6 (coarse)
            const float* wp1 = w1 + (size_t)(CCH + 108) * HID + cg * 4;
            const float* wp2 = w1 + cg * 4;
#pragma unroll 5
            for (int kk = 0; kk < CHK; kk++) {
                float4 fv = *(const float4*)&sb[kk * SFS + pg * 4];
                const float* wpk = (kk < 20) ? (wp1 + (size_t)kk * HID)
                                             : (wp2 + (size_t)(kk - 20) * HID);
                ulonglong2 w = *(const ulonglong2*)wpk;
                ull f0 = pack2(fv.x, fv.x);
                ull f1 = pack2(fv.y, fv.y);
                ull f2v = pack2(fv.z, fv.z);
                ull f3 = pack2(fv.w, fv.w);
                acc2[0][0] = fma2(w.x, f0, acc2[0][0]);
                acc2[0][1] = fma2(w.y, f0, acc2[0][1]);
                acc2[1][0] = fma2(w.x, f1, acc2[1][0]);
                acc2[1][1] = fma2(w.y, f1, acc2[1][1]);
                acc2[2][0] = fma2(w.x, f2v, acc2[2][0]);
                acc2[2][1] = fma2(w.y, f2v, acc2[2][1]);
                acc2[3][0] = fma2(w.x, f3, acc2[3][0]);
                acc2[3][1] = fma2(w.y, f3, acc2[3][1]);
            }
        }

        // combine + store gathered chunk c+1 into the other sfb buffer
        if (c < 4) {
            int k1 = (c + 1) * CHK;
            float* so = sfb + ((c + 1) & 1) * (CHK * SFS);
#pragma unroll
            for (int s = 0; s < 2; s++) {
                int task = s * 256 + t;
                if (task < NTASK) {
                    int kk = task >> 4, p = task & 15;
                    int ch = k1 + kk;
                    float4 par, mk;
                    if (ch < FCH) { par = fpar[p]; mk = fmsk[p]; }
                    else          { par = cpar[p]; mk = cmsk[p]; }
                    bool xo = par.z != 0.0f, s1 = par.w != 0.0f;
                    float vx00 = xo ? a0[s].y : a0[s].x;
                    float t10  = xo ? b0[s].x : a0[s].y;
                    float vx10 = s1 ? t10 : vx00;
                    float vx01 = xo ? a1[s].y : a1[s].x;
                    float t11  = xo ? b1r[s].x : a1[s].y;
                    float vx11 = s1 ? t11 : vx01;
                    float owx = 1.0f - par.x, owy = 1.0f - par.y;
                    so[kk * SFS + p] = vx00 * mk.x * (owx * owy) + vx10 * mk.y * (par.x * owy)
                                     + vx01 * mk.z * (owx * par.y) + vx11 * mk.w * (par.x * par.y);
                }
            }
        }
    }
    __syncthreads();   // all compute done; cbl region free -> reuse as part

    // epilogue: relu + w2 partials per thread, butterfly over the warp's 32 cgs
    float pr[4][7];
#pragma unroll
    for (int i = 0; i < 4; i++) {
        float h0, h1, h2, h3;
        unpack2(acc2[i][0], h0, h1);
        unpack2(acc2[i][1], h2, h3);
        h0 = fmaxf(h0, 0.0f); h1 = fmaxf(h1, 0.0f);
        h2 = fmaxf(h2, 0.0f); h3 = fmaxf(h3, 0.0f);
        const float* w20 = &w2s[(cg * 4 + 0) * 7];
        const float* w21 = w20 + 7;
        const float* w22 = w20 + 14;
        const float* w23 = w20 + 21;
#pragma unroll
        for (int k = 0; k < 7; k++)
            pr[i][k] = h0 * w20[k] + h1 * w21[k] + h2 * w22[k] + h3 * w23[k];
    }
#pragma unroll
    for (int off = 16; off > 0; off >>= 1) {
#pragma unroll
        for (int i = 0; i < 4; i++)
#pragma unroll
            for (int k = 0; k < 7; k++)
                pr[i][k] += __shfl_xor_sync(0xffffffffu, pr[i][k], off);
    }
    int wrp = t >> 5;   // warps {2w, 2w+1} share pg=w, cover cgs 0-31 / 32-63
    if ((t & 31) == 0) {
#pragma unroll
        for (int i = 0; i < 4; i++)
#pragma unroll
            for (int k = 0; k < 7; k++)
                part[((wrp & 1) * 16 + (pg * 4 + i)) * 7 + k] = pr[i][k];
    }
    __syncthreads();

    // final: add the two warp-halves + b2, write rend[b][k][p]
    if (t < 16 * 7) {
        int p = t / 7, k = t % 7;
        float s = b2[k] + part[p * 7 + k] + part[(16 + p) * 7 + k];
        rend[((size_t)b * CCH + k) * NPTS + (bp0 & 1023) + p] = s;
    }
}

extern "C" void kernel_launch(void* const* d_in, const int* in_sizes, int n_in,
                              void* d_out, int out_size) {
    (void)in_sizes; (void)n_in; (void)out_size;
    const float* fine     = (const float*)d_in[0];
    const float* coarse   = (const float*)d_in[1];
    const float* w1       = (const float*)d_in[2];
    const float* b1       = (const float*)d_in[3];
    const float* w2       = (const float*)d_in[4];
    const float* b2       = (const float*)d_in[5];
    const float* over_gen = (const float*)d_in[6];
    const float* coverage = (const float*)d_in[7];

    float* rend = (float*)d_out;                 // [16][7][1024]
    float* pts  = rend + NB * CCH * NPTS;        // [16][1024][2]

    cudaFuncSetAttribute(k_prep,  cudaFuncAttributeMaxDynamicSharedMemorySize, PR_SMEM);
    cudaFuncSetAttribute(k_fused, cudaFuncAttributeMaxDynamicSharedMemorySize, FU_TOT * 4);

    k_prep<<<NB, 1024, PR_SMEM>>>(coarse, over_gen, coverage, pts);
    k_fused<<<NB * NPTS / 16, 256, FU_TOT * 4>>>(fine, coarse, w1, b1, w2, b2, pts, rend);
}

// round 14
// speedup vs baseline: 1.5035x; 1.1729x over previous
#include <cuda_runtime.h>
#include <stdint.h>

#define NB    16
#define CCH   7
#define FCH   128
#define CW    64
#define FW    256
#define NPTS  1024
#define NIMP  768
#define NCOV  256
#define NOVER 7168
#define HID   256
#define FEATC 135

typedef unsigned long long ull;

// ───────────────────────── helpers ─────────────────────────

__device__ __forceinline__ ull fma2(ull a, ull b, ull c) {
    ull d;
    asm("fma.rn.f32x2 %0, %1, %2, %3;" : "=l"(d) : "l"(a), "l"(b), "l"(c));
    return d;
}
__device__ __forceinline__ ull pack2(float lo, float hi) {
    ull d;
    asm("mov.b64 %0, {%1, %2};" : "=l"(d) : "f"(lo), "f"(hi));
    return d;
}
__device__ __forceinline__ void unpack2(ull v, float& lo, float& hi) {
    asm("mov.b64 {%0, %1}, %2;" : "=f"(lo), "=f"(hi) : "l"(v));
}
__device__ __forceinline__ void cp_async16(void* dst, const void* src) {
    unsigned d = (unsigned)__cvta_generic_to_shared(dst);
    asm volatile("cp.async.ca.shared.global [%0], [%1], 16;\n" :: "r"(d), "l"(src));
}
#define CP_COMMIT() asm volatile("cp.async.commit_group;\n" ::: "memory")
#define CP_WAIT0()  asm volatile("cp.async.wait_group 0;\n" ::: "memory")

struct BL {
    int   i00, i01, i10, i11;
    float m00, m01, m10, m11;
    float wx, wy;
};

// Replicates the reference's point_sample coordinate math with explicit
// rounding (no FMA contraction) so the top-k selection is bit-stable.
__device__ __forceinline__ void bl_setup(float px, float py, int W, BL& o) {
    float gx = __fsub_rn(__fmul_rn(2.0f, px), 1.0f);
    float gy = __fsub_rn(__fmul_rn(2.0f, py), 1.0f);
    float x  = __fmul_rn(__fsub_rn(__fmul_rn(__fadd_rn(gx, 1.0f), (float)W), 1.0f), 0.5f);
    float y  = __fmul_rn(__fsub_rn(__fmul_rn(__fadd_rn(gy, 1.0f), (float)W), 1.0f), 0.5f);
    float x0f = floorf(x), y0f = floorf(y);
    o.wx = __fsub_rn(x, x0f);
    o.wy = __fsub_rn(y, y0f);
    float x1f = __fadd_rn(x0f, 1.0f), y1f = __fadd_rn(y0f, 1.0f);
    float wm1 = (float)(W - 1);
    bool vx0 = (x0f >= 0.0f) && (x0f <= wm1);
    bool vx1 = (x1f >= 0.0f) && (x1f <= wm1);
    bool vy0 = (y0f >= 0.0f) && (y0f <= wm1);
    bool vy1 = (y1f >= 0.0f) && (y1f <= wm1);
    int ix0 = min(max((int)x0f, 0), W - 1);
    int ix1 = min(max((int)x1f, 0), W - 1);
    int iy0 = min(max((int)y0f, 0), W - 1);
    int iy1 = min(max((int)y1f, 0), W - 1);
    o.i00 = iy0 * W + ix0; o.i01 = iy0 * W + ix1;
    o.i10 = iy1 * W + ix0; o.i11 = iy1 * W + ix1;
    o.m00 = (vx0 && vy0) ? 1.0f : 0.0f;
    o.m01 = (vx1 && vy0) ? 1.0f : 0.0f;
    o.m10 = (vx0 && vy1) ? 1.0f : 0.0f;
    o.m11 = (vx1 && vy1) ? 1.0f : 0.0f;
}

__device__ __forceinline__ float bl_sample(const float* __restrict__ plane, const BL& o) {
    float v00 = __fmul_rn(plane[o.i00], o.m00);
    float v01 = __fmul_rn(plane[o.i01], o.m01);
    float v10 = __fmul_rn(plane[o.i10], o.m10);
    float v11 = __fmul_rn(plane[o.i11], o.m11);
    float owx = __fsub_rn(1.0f, o.wx), owy = __fsub_rn(1.0f, o.wy);
    float t0 = __fmul_rn(__fmul_rn(v00, owx),  owy);
    float t1 = __fmul_rn(__fmul_rn(v01, o.wx), owy);
    float t2 = __fmul_rn(__fmul_rn(v10, owx),  o.wy);
    float t3 = __fmul_rn(__fmul_rn(v11, o.wx), o.wy);
    return __fadd_rn(__fadd_rn(__fadd_rn(t0, t1), t2), t3);
}

// ───────────────────────── k_prep ─────────────────────────
// One block per batch. top2 -> smem, keys -> smem, early-exit radix select,
// hybrid smem/shfl bitonic sort of <=1024 survivors, emit points.
#define PR_ST2   0
#define PR_KEYS  32768
#define PR_CAND  90112
#define PR_BUF   147456
#define PR_HIST  155648
#define PR_SCAN  156672
#define PR_CTRL  156800
#define PR_SMEM  156832

__global__ void __launch_bounds__(1024) k_prep(const float* __restrict__ coarse,
                                               const float* __restrict__ over_gen,
                                               const float* __restrict__ coverage,
                                               float* __restrict__ pts_out) {
    extern __shared__ char smraw[];
    float*    st2  = (float*)(smraw + PR_ST2);
    ull*      keys = (ull*)(smraw + PR_KEYS);
    ull*      cand = (ull*)(smraw + PR_CAND);
    ull*      buf  = (ull*)(smraw + PR_BUF);
    unsigned* hist = (unsigned*)(smraw + PR_HIST);
    unsigned* wsum = (unsigned*)(smraw + PR_SCAN);   // 8 warp sums
    int*      s_sel  = (int*)(smraw + PR_CTRL);
    int*      s_rank = (int*)(smraw + PR_CTRL + 4);
    int*      s_wcnt = (int*)(smraw + PR_CTRL + 8);
    int*      s_ccnt = (int*)(smraw + PR_CTRL + 12);

    int b = blockIdx.x;
    int t = threadIdx.x;

    // top-2 over 7 channels, into smem
    const float* cb = coarse + (size_t)b * CCH * 4096;
    for (int pix = t; pix < 4096; pix += 1024) {
        float m1 = __int_as_float(0xff800000), m2 = m1;
#pragma unroll
        for (int c = 0; c < CCH; c++) {
            float v = cb[c * 4096 + pix];
            if (v > m1) { m2 = m1; m1 = v; }
            else if (v > m2) { m2 = v; }
        }
        st2[pix]        = m1;
        st2[4096 + pix] = m2;
    }
    if (t == 0) { *s_wcnt = 0; }
    __syncthreads();

    // uncertainty + composite keys (value desc via order-mapped ~bits, idx asc)
    const float2* og = (const float2*)over_gen + (size_t)b * NOVER;
    for (int i = t; i < NOVER; i += 1024) {
        float2 p = og[i];
        BL o;
        bl_setup(p.x, p.y, CW, o);
        float s0 = bl_sample(st2, o);
        float s1 = bl_sample(st2 + 4096, o);
        float un = -__fsub_rn(s0, s1);
        unsigned u = __float_as_uint(un);
        u = (u & 0x80000000u) ? ~u : (u ^ 0x80000000u);
        keys[i] = ((ull)(~u) << 13) | (unsigned)i;
    }
    __syncthreads();

    // early-exit radix select
    ull* src = keys;
    ull* dstc = cand;
    int m = NOVER;
    int rank = NIMP;
    int total = 0;
    for (int byte = 5; byte >= 0; byte--) {
        int sh = byte * 8;
        if (t < 256) hist[t] = 0;
        __syncthreads();
        for (int i = t; i < m; i += 1024)
            atomicAdd(&hist[(unsigned)(src[i] >> sh) & 255u], 1u);
        __syncthreads();
        // shfl inclusive scan of the 256-bin histogram (threads 0..255)
        unsigned hv = (t < 256) ? hist[t] : 0;
        unsigned sv = hv;
#pragma unroll
        for (int off = 1; off < 32; off <<= 1) {
            unsigned n = __shfl_up_sync(0xffffffffu, sv, off);
            if ((t & 31) >= off) sv += n;
        }
        if (t < 256 && (t & 31) == 31) wsum[t >> 5] = sv;
        __syncthreads();
        if (t == 0) {
            unsigned run = 0;
#pragma unroll
            for (int w8 = 0; w8 < 8; w8++) { unsigned x = wsum[w8]; wsum[w8] = run; run += x; }
            *s_ccnt = 0;
        }
        __syncthreads();
        if (t < 256) {
            unsigned incl = sv + wsum[t >> 5];
            unsigned excl = incl - hv;
            if (excl < (unsigned)rank && (unsigned)rank <= incl) {
                *s_sel  = t;
                *s_rank = rank - (int)excl;
            }
        }
        __syncthreads();
        int sel = *s_sel;
        rank = *s_rank;
        // partition: digit<sel -> definite winner; ==sel -> candidate
        for (int i = t; i < m; i += 1024) {
            ull k = src[i];
            int d = (int)((unsigned)(k >> sh) & 255u);
            if (d < sel)       buf[atomicAdd(s_wcnt, 1)] = k;
            else if (d == sel) dstc[atomicAdd(s_ccnt, 1)] = k;
        }
        __syncthreads();
        m = *s_ccnt;
        int w = *s_wcnt;
        if (w + m <= 1024) {
            for (int i = t; i < m; i += 1024) buf[w + i] = dstc[i];
            total = w + m;
            break;
        }
        ull* tmp = src; src = dstc; dstc = tmp;
        __syncthreads();
    }
    __syncthreads();

    // hybrid bitonic sort: element in register, smem for j>=32, shfl for j<=16
    ull v = (t < total) ? buf[t] : ~0ull;
    for (unsigned k = 2; k <= 1024; k <<= 1) {
        unsigned j = k >> 1;
        for (; j >= 32; j >>= 1) {
            buf[t] = v;
            __syncthreads();
            ull c = buf[t ^ j];
            bool keepmin = (((t & k) == 0) == ((t & j) == 0));
            v = keepmin ? (v < c ? v : c) : (v < c ? c : v);
            __syncthreads();
        }
        for (; j > 0; j >>= 1) {
            ull c = __shfl_xor_sync(0xffffffffu, v, j);
            bool keepmin = (((t & k) == 0) == ((t & j) == 0));
            v = keepmin ? (v < c ? v : c) : (v < c ? c : v);
        }
    }

    float* dst = pts_out + (size_t)b * NPTS * 2;
    if (t < NIMP) {
        int n = (int)(v & 0x1FFFull);
        float2 p = og[n];
        dst[t * 2 + 0] = p.x;
        dst[t * 2 + 1] = p.y;
    } else {
        int i = t - NIMP;
        float2 p = ((const float2*)coverage)[(size_t)b * NCOV + i];
        dst[(NIMP + i) * 2 + 0] = p.x;
        dst[(NIMP + i) * 2 + 1] = p.y;
    }
}

// ───────────────────────── k_fused ─────────────────────────
// R10 skeleton (best measured): 1024 CTAs x 16 points, 256 threads,
// thread tile 4pt x 4col (cg=t&63, pg=t>>6). Paired-x gather (LDG.64).
// w1 staged per-chunk in smem via cp.async (single buffer, in-chunk wait),
// two barriers per chunk. ONLY change vs R10: reg cap for 4 CTAs/SM.
// smem floats: sfb 2*540 | w1s 6912 (reused as part) | w2s 1792 | params 384
#define FU_SFB   0
#define FU_W1S   1080
#define FU_W2S   8248
#define FU_CBL   10040
#define FU_TOT   10424   // floats -> 41696 bytes

#define CHK   27
#define SFS   20        // sfb row stride
#define NTASK (CHK * 16)

__global__ void __launch_bounds__(256, 4) k_fused(
    const float* __restrict__ fine, const float* __restrict__ coarse,
    const float* __restrict__ w1, const float* __restrict__ b1,
    const float* __restrict__ w2, const float* __restrict__ b2,
    const float* __restrict__ pts, float* __restrict__ rend)
{
    extern __shared__ float sm[];
    float*  sfb  = sm + FU_SFB;        // [2][27*20]
    float*  w1s  = sm + FU_W1S;        // [27][256]; reused as part
    float*  w2s  = sm + FU_W2S;        // [256][7]
    int4*   fidx = (int4*)(sm + FU_CBL);          // [16] halved f2 idx
    float4* fpar = (float4*)(sm + FU_CBL + 64);   // [16] (wx, wy, xodd, sel1)
    float4* fmsk = (float4*)(sm + FU_CBL + 128);  // [16] (m00,m01,m10,m11)
    int4*   cidx = (int4*)(sm + FU_CBL + 192);
    float4* cpar = (float4*)(sm + FU_CBL + 256);
    float4* cmsk = (float4*)(sm + FU_CBL + 320);
    float*  part = w1s;                // reused after mainloop

    int t   = threadIdx.x;
    int bp0 = blockIdx.x * 16;
    int b   = bp0 >> 10;
    int cg  = t & 63;               // col group: cols cg*4 .. cg*4+3
    int pg  = t >> 6;               // point group: pts pg*4 .. pg*4+3

    // prologue: per-point params (t<16 fine, 16<=t<32 coarse)
    if (t < 32) {
        int p_ = t & 15;
        int W  = (t < 16) ? FW : CW;
        float2 p = ((const float2*)pts)[bp0 + p_];
        BL o;
        bl_setup(p.x, p.y, W, o);
        int ix0 = o.i00 & (W - 1);
        int ix1 = o.i01 & (W - 1);
        int rb0 = o.i00 - ix0;
        int rb1 = o.i10 - ix0;
        int eb  = ix0 & ~1;
        int c2  = min(eb + 2, W - 2);
        int4  idx = make_int4((rb0 + eb) >> 1, (rb0 + c2) >> 1,
                              (rb1 + eb) >> 1, (rb1 + c2) >> 1);
        float4 par = make_float4(o.wx, o.wy, (float)(ix0 & 1),
                                 (ix1 == ix0 + 1) ? 1.0f : 0.0f);
        float4 msk = make_float4(o.m00, o.m01, o.m10, o.m11);
        if (t < 16) { fidx[p_] = idx; fpar[p_] = par; fmsk[p_] = msk; }
        else        { cidx[p_] = idx; cpar[p_] = par; cmsk[p_] = msk; }
    }
    for (int i = t; i < HID * 7; i += 256) w2s[i] = w2[i];

    // accumulators: 4 pts x 4 cols as 4x2 packed f32x2, init with bias
    ull acc2[4][2];
    {
        ull bv0 = pack2(b1[cg * 4 + 0], b1[cg * 4 + 1]);
        ull bv1 = pack2(b1[cg * 4 + 2], b1[cg * 4 + 3]);
#pragma unroll
        for (int i = 0; i < 4; i++) { acc2[i][0] = bv0; acc2[i][1] = bv1; }
    }
    __syncthreads();

    float2 a0[2], a1[2], b0[2], b1r[2];

    // gather chunk 0 (fine channels 0..26): issue then combine into sfb[0]
#pragma unroll
    for (int s = 0; s < 2; s++) {
        int task = s * 256 + t;
        if (task < NTASK) {
            int kk = task >> 4, p = task & 15;
            const float2* pl2 = (const float2*)(fine + ((size_t)b * FCH + kk) * 65536);
            int4 ix = fidx[p];
            float4 par = fpar[p];
            a0[s] = pl2[ix.x]; a1[s] = pl2[ix.z];
            b0[s] = make_float2(0.f, 0.f); b1r[s] = b0[s];
            if (par.z != 0.0f) { b0[s] = pl2[ix.y]; b1r[s] = pl2[ix.w]; }
        }
    }
#pragma unroll
    for (int s = 0; s < 2; s++) {
        int task = s * 256 + t;
        if (task < NTASK) {
            int kk = task >> 4, p = task & 15;
            float4 par = fpar[p];
            float4 mk  = fmsk[p];
            bool xo = par.z != 0.0f, s1 = par.w != 0.0f;
            float vx00 = xo ? a0[s].y : a0[s].x;
            float t10  = xo ? b0[s].x : a0[s].y;
            float vx10 = s1 ? t10 : vx00;
            float vx01 = xo ? a1[s].y : a1[s].x;
            float t11  = xo ? b1r[s].x : a1[s].y;
            float vx11 = s1 ? t11 : vx01;
            float owx = 1.0f - par.x, owy = 1.0f - par.y;
            sfb[kk * SFS + p] = vx00 * mk.x * (owx * owy) + vx10 * mk.y * (par.x * owy)
                              + vx01 * mk.z * (owx * par.y) + vx11 * mk.w * (par.x * par.y);
        }
    }

    for (int c = 0; c < 5; c++) {
        __syncthreads();   // sfb[c&1] visible; prior compute done -> w1s free
        int k0 = c * CHK;
        // cp.async w1 chunk c (row kk -> w1s[kk*256 + ...])
        for (int i = t; i < CHK * 64; i += 256) {
            int kk = i >> 6, q = i & 63;
            int row = k0 + kk;
            int srow = (row < FCH) ? (CCH + row) : (row - FCH);
            cp_async16(&w1s[kk * 256 + q * 4], w1 + (size_t)srow * HID + q * 4);
        }
        CP_COMMIT();
        // issue paired-x gather LDGs for chunk c+1
        if (c < 4) {
            int k1 = (c + 1) * CHK;
#pragma unroll
            for (int s = 0; s < 2; s++) {
                int task = s * 256 + t;
                if (task < NTASK) {
                    int kk = task >> 4, p = task & 15;
                    int ch = k1 + kk;
                    const float2* pl2;
                    int4 ix; float4 par;
                    if (ch < FCH) {
                        pl2 = (const float2*)(fine + ((size_t)b * FCH + ch) * 65536);
                        ix = fidx[p]; par = fpar[p];
                    } else {
                        pl2 = (const float2*)(coarse + ((size_t)b * CCH + (ch - FCH)) * 4096);
                        ix = cidx[p]; par = cpar[p];
                    }
                    a0[s] = pl2[ix.x]; a1[s] = pl2[ix.z];
                    b0[s] = make_float2(0.f, 0.f); b1r[s] = b0[s];
                    if (par.z != 0.0f) { b0[s] = pl2[ix.y]; b1r[s] = pl2[ix.w]; }
                }
            }
        }
        CP_WAIT0();
        __syncthreads();   // w1s chunk c ready for all threads

        // compute chunk c: 4pt x 4col packed f32x2
        const float* sb = sfb + (c & 1) * (CHK * SFS);
#pragma unroll 3
        for (int kk = 0; kk < CHK; kk++) {
            float4 fv = *(const float4*)&sb[kk * SFS + pg * 4];      // broadcast
            ulonglong2 w = *(const ulonglong2*)&w1s[kk * 256 + cg * 4];
            ull f0 = pack2(fv.x, fv.x);
            ull f1 = pack2(fv.y, fv.y);
            ull f2v = pack2(fv.z, fv.z);
            ull f3 = pack2(fv.w, fv.w);
            acc2[0][0] = fma2(w.x, f0, acc2[0][0]);
            acc2[0][1] = fma2(w.y, f0, acc2[0][1]);
            acc2[1][0] = fma2(w.x, f1, acc2[1][0]);
            acc2[1][1] = fma2(w.y, f1, acc2[1][1]);
            acc2[2][0] = fma2(w.x, f2v, acc2[2][0]);
            acc2[2][1] = fma2(w.y, f2v, acc2[2][1]);
            acc2[3][0] = fma2(w.x, f3, acc2[3][0]);
            acc2[3][1] = fma2(w.y, f3, acc2[3][1]);
        }

        // combine + store gathered chunk c+1 into the other sfb buffer
        if (c < 4) {
            int k1 = (c + 1) * CHK;
            float* so = sfb + ((c + 1) & 1) * (CHK * SFS);
#pragma unroll
            for (int s = 0; s < 2; s++) {
                int task = s * 256 + t;
                if (task < NTASK) {
                    int kk = task >> 4, p = task & 15;
                    int ch = k1 + kk;
                    float4 par, mk;
                    if (ch < FCH) { par = fpar[p]; mk = fmsk[p]; }
                    else          { par = cpar[p]; mk = cmsk[p]; }
                    bool xo = par.z != 0.0f, s1 = par.w != 0.0f;
                    float vx00 = xo ? a0[s].y : a0[s].x;
                    float t10  = xo ? b0[s].x : a0[s].y;
                    float vx10 = s1 ? t10 : vx00;
                    float vx01 = xo ? a1[s].y : a1[s].x;
                    float t11  = xo ? b1r[s].x : a1[s].y;
                    float vx11 = s1 ? t11 : vx01;
                    float owx = 1.0f - par.x, owy = 1.0f - par.y;
                    so[kk * SFS + p] = vx00 * mk.x * (owx * owy) + vx10 * mk.y * (par.x * owy)
                                     + vx01 * mk.z * (owx * par.y) + vx11 * mk.w * (par.x * par.y);
                }
            }
        }
    }
    __syncthreads();   // all compute done; w1s free -> reuse as part

    // epilogue: relu + w2 partials per thread, butterfly over the warp's 32 cgs
    float pr[4][7];
#pragma unroll
    for (int i = 0; i < 4; i++) {
        float h0, h1, h2, h3;
        unpack2(acc2[i][0], h0, h1);
        unpack2(acc2[i][1], h2, h3);
        h0 = fmaxf(h0, 0.0f); h1 = fmaxf(h1, 0.0f);
        h2 = fmaxf(h2, 0.0f); h3 = fmaxf(h3, 0.0f);
        const float* w20 = &w2s[(cg * 4 + 0) * 7];
        const float* w21 = w20 + 7;
        const float* w22 = w20 + 14;
        const float* w23 = w20 + 21;
#pragma unroll
        for (int k = 0; k < 7; k++)
            pr[i][k] = h0 * w20[k] + h1 * w21[k] + h2 * w22[k] + h3 * w23[k];
    }
#pragma unroll
    for (int off = 16; off > 0; off >>= 1) {
#pragma unroll
        for (int i = 0; i < 4; i++)
#pragma unroll
            for (int k = 0; k < 7; k++)
                pr[i][k] += __shfl_xor_sync(0xffffffffu, pr[i][k], off);
    }
    int wrp = t >> 5;   // warps {2w, 2w+1} share pg=w, cover cgs 0-31 / 32-63
    if ((t & 31) == 0) {
#pragma unroll
        for (int i = 0; i < 4; i++)
#pragma unroll
            for (int k = 0; k < 7; k++)
                part[((wrp & 1) * 16 + (pg * 4 + i)) * 7 + k] = pr[i][k];
    }
    __syncthreads();

    // final: add the two warp-halves + b2, write rend[b][k][p]
    if (t < 16 * 7) {
        int p = t / 7, k = t % 7;
        float s = b2[k] + part[p * 7 + k] + part[(16 + p) * 7 + k];
        rend[((size_t)b * CCH + k) * NPTS + (bp0 & 1023) + p] = s;
    }
}

extern "C" void kernel_launch(void* const* d_in, const int* in_sizes, int n_in,
                              void* d_out, int out_size) {
    (void)in_sizes; (void)n_in; (void)out_size;
    const float* fine     = (const float*)d_in[0];
    const float* coarse   = (const float*)d_in[1];
    const float* w1       = (const float*)d_in[2];
    const float* b1       = (const float*)d_in[3];
    const float* w2       = (const float*)d_in[4];
    const float* b2       = (const float*)d_in[5];
    const float* over_gen = (const float*)d_in[6];
    const float* coverage = (const float*)d_in[7];

    float* rend = (float*)d_out;                 // [16][7][1024]
    float* pts  = rend + NB * CCH * NPTS;        // [16][1024][2]

    cudaFuncSetAttribute(k_prep,  cudaFuncAttributeMaxDynamicSharedMemorySize, PR_SMEM);
    cudaFuncSetAttribute(k_fused, cudaFuncAttributeMaxDynamicSharedMemorySize, FU_TOT * 4);

    k_prep<<<NB, 1024, PR_SMEM>>>(coarse, over_gen, coverage, pts);
    k_fused<<<NB * NPTS / 16, 256, FU_TOT * 4>>>(fine, coarse, w1, b1, w2, b2, pts, rend);
}

// round 16
// speedup vs baseline: 1.6277x; 1.0827x over previous
#include <cuda_runtime.h>
#include <stdint.h>

#define NB    16
#define CCH   7
#define FCH   128
#define CW    64
#define FW    256
#define NPTS  1024
#define NIMP  768
#define NCOV  256
#define NOVER 7168
#define HID   256
#define FEATC 135

typedef unsigned long long ull;

// ───────────────────────── helpers ─────────────────────────

__device__ __forceinline__ ull fma2(ull a, ull b, ull c) {
    ull d;
    asm("fma.rn.f32x2 %0, %1, %2, %3;" : "=l"(d) : "l"(a), "l"(b), "l"(c));
    return d;
}
__device__ __forceinline__ ull pack2(float lo, float hi) {
    ull d;
    asm("mov.b64 %0, {%1, %2};" : "=l"(d) : "f"(lo), "f"(hi));
    return d;
}
__device__ __forceinline__ void unpack2(ull v, float& lo, float& hi) {
    asm("mov.b64 {%0, %1}, %2;" : "=f"(lo), "=f"(hi) : "l"(v));
}
__device__ __forceinline__ void cp_async16(void* dst, const void* src) {
    unsigned d = (unsigned)__cvta_generic_to_shared(dst);
    asm volatile("cp.async.ca.shared.global [%0], [%1], 16;\n" :: "r"(d), "l"(src));
}
#define CP_COMMIT() asm volatile("cp.async.commit_group;\n" ::: "memory")
#define CP_WAIT0()  asm volatile("cp.async.wait_group 0;\n" ::: "memory")

struct BL {
    int   i00, i01, i10, i11;
    float m00, m01, m10, m11;
    float wx, wy;
};

// Replicates the reference's point_sample coordinate math with explicit
// rounding (no FMA contraction) so the top-k selection is bit-stable.
__device__ __forceinline__ void bl_setup(float px, float py, int W, BL& o) {
    float gx = __fsub_rn(__fmul_rn(2.0f, px), 1.0f);
    float gy = __fsub_rn(__fmul_rn(2.0f, py), 1.0f);
    float x  = __fmul_rn(__fsub_rn(__fmul_rn(__fadd_rn(gx, 1.0f), (float)W), 1.0f), 0.5f);
    float y  = __fmul_rn(__fsub_rn(__fmul_rn(__fadd_rn(gy, 1.0f), (float)W), 1.0f), 0.5f);
    float x0f = floorf(x), y0f = floorf(y);
    o.wx = __fsub_rn(x, x0f);
    o.wy = __fsub_rn(y, y0f);
    float x1f = __fadd_rn(x0f, 1.0f), y1f = __fadd_rn(y0f, 1.0f);
    float wm1 = (float)(W - 1);
    bool vx0 = (x0f >= 0.0f) && (x0f <= wm1);
    bool vx1 = (x1f >= 0.0f) && (x1f <= wm1);
    bool vy0 = (y0f >= 0.0f) && (y0f <= wm1);
    bool vy1 = (y1f >= 0.0f) && (y1f <= wm1);
    int ix0 = min(max((int)x0f, 0), W - 1);
    int ix1 = min(max((int)x1f, 0), W - 1);
    int iy0 = min(max((int)y0f, 0), W - 1);
    int iy1 = min(max((int)y1f, 0), W - 1);
    o.i00 = iy0 * W + ix0; o.i01 = iy0 * W + ix1;
    o.i10 = iy1 * W + ix0; o.i11 = iy1 * W + ix1;
    o.m00 = (vx0 && vy0) ? 1.0f : 0.0f;
    o.m01 = (vx1 && vy0) ? 1.0f : 0.0f;
    o.m10 = (vx0 && vy1) ? 1.0f : 0.0f;
    o.m11 = (vx1 && vy1) ? 1.0f : 0.0f;
}

__device__ __forceinline__ float bl_sample(const float* __restrict__ plane, const BL& o) {
    float v00 = __fmul_rn(plane[o.i00], o.m00);
    float v01 = __fmul_rn(plane[o.i01], o.m01);
    float v10 = __fmul_rn(plane[o.i10], o.m10);
    float v11 = __fmul_rn(plane[o.i11], o.m11);
    float owx = __fsub_rn(1.0f, o.wx), owy = __fsub_rn(1.0f, o.wy);
    float t0 = __fmul_rn(__fmul_rn(v00, owx),  owy);
    float t1 = __fmul_rn(__fmul_rn(v01, o.wx), owy);
    float t2 = __fmul_rn(__fmul_rn(v10, owx),  o.wy);
    float t3 = __fmul_rn(__fmul_rn(v11, o.wx), o.wy);
    return __fadd_rn(__fadd_rn(__fadd_rn(t0, t1), t2), t3);
}

// ───────────────────────── k_prep ─────────────────────────
// One block per batch. top2 -> smem, keys -> smem, early-exit radix select
// with WARP-AGGREGATED partition atomics (1 atomic/warp/counter instead of
// 1/lane), hybrid smem/shfl bitonic sort of <=1024 survivors, emit points.
#define PR_ST2   0
#define PR_KEYS  32768
#define PR_CAND  90112
#define PR_BUF   147456
#define PR_HIST  155648
#define PR_SCAN  156672
#define PR_CTRL  156800
#define PR_SMEM  156832

__global__ void __launch_bounds__(1024) k_prep(const float* __restrict__ coarse,
                                               const float* __restrict__ over_gen,
                                               const float* __restrict__ coverage,
                                               float* __restrict__ pts_out) {
    extern __shared__ char smraw[];
    float*    st2  = (float*)(smraw + PR_ST2);
    ull*      keys = (ull*)(smraw + PR_KEYS);
    ull*      cand = (ull*)(smraw + PR_CAND);
    ull*      buf  = (ull*)(smraw + PR_BUF);
    unsigned* hist = (unsigned*)(smraw + PR_HIST);
    unsigned* wsum = (unsigned*)(smraw + PR_SCAN);   // 8 warp sums
    int*      s_sel  = (int*)(smraw + PR_CTRL);
    int*      s_rank = (int*)(smraw + PR_CTRL + 4);
    int*      s_wcnt = (int*)(smraw + PR_CTRL + 8);
    int*      s_ccnt = (int*)(smraw + PR_CTRL + 12);

    int b = blockIdx.x;
    int t = threadIdx.x;
    int lane = t & 31;

    // top-2 over 7 channels, into smem
    const float* cb = coarse + (size_t)b * CCH * 4096;
    for (int pix = t; pix < 4096; pix += 1024) {
        float m1 = __int_as_float(0xff800000), m2 = m1;
#pragma unroll
        for (int c = 0; c < CCH; c++) {
            float v = cb[c * 4096 + pix];
            if (v > m1) { m2 = m1; m1 = v; }
            else if (v > m2) { m2 = v; }
        }
        st2[pix]        = m1;
        st2[4096 + pix] = m2;
    }
    if (t == 0) { *s_wcnt = 0; }
    __syncthreads();

    // uncertainty + composite keys (value desc via order-mapped ~bits, idx asc)
    const float2* og = (const float2*)over_gen + (size_t)b * NOVER;
    for (int i = t; i < NOVER; i += 1024) {
        float2 p = og[i];
        BL o;
        bl_setup(p.x, p.y, CW, o);
        float s0 = bl_sample(st2, o);
        float s1 = bl_sample(st2 + 4096, o);
        float un = -__fsub_rn(s0, s1);
        unsigned u = __float_as_uint(un);
        u = (u & 0x80000000u) ? ~u : (u ^ 0x80000000u);
        keys[i] = ((ull)(~u) << 13) | (unsigned)i;
    }
    __syncthreads();

    // early-exit radix select
    ull* src = keys;
    ull* dstc = cand;
    int m = NOVER;
    int rank = NIMP;
    int total = 0;
    for (int byte = 5; byte >= 0; byte--) {
        int sh = byte * 8;
        if (t < 256) hist[t] = 0;
        __syncthreads();
        for (int i = t; i < m; i += 1024)
            atomicAdd(&hist[(unsigned)(src[i] >> sh) & 255u], 1u);
        __syncthreads();
        // shfl inclusive scan of the 256-bin histogram (threads 0..255)
        unsigned hv = (t < 256) ? hist[t] : 0;
        unsigned sv = hv;
#pragma unroll
        for (int off = 1; off < 32; off <<= 1) {
            unsigned n = __shfl_up_sync(0xffffffffu, sv, off);
            if (lane >= off) sv += n;
        }
        if (t < 256 && lane == 31) wsum[t >> 5] = sv;
        __syncthreads();
        if (t == 0) {
            unsigned run = 0;
#pragma unroll
            for (int w8 = 0; w8 < 8; w8++) { unsigned x = wsum[w8]; wsum[w8] = run; run += x; }
            *s_ccnt = 0;
        }
        __syncthreads();
        if (t < 256) {
            unsigned incl = sv + wsum[t >> 5];
            unsigned excl = incl - hv;
            if (excl < (unsigned)rank && (unsigned)rank <= incl) {
                *s_sel  = t;
                *s_rank = rank - (int)excl;
            }
        }
        __syncthreads();
        int sel = *s_sel;
        rank = *s_rank;
        // partition with warp-aggregated atomics; uniform trip count so the
        // ballots stay converged.
        int iters = (m + 1023) >> 10;
        for (int it = 0; it < iters; it++) {
            int i = it * 1024 + t;
            bool valid = (i < m);
            ull k = valid ? src[i] : 0ull;
            int d = valid ? (int)((unsigned)(k >> sh) & 255u) : 256;
            bool isw = (d < sel), isc = (d == sel);
            unsigned mw = __ballot_sync(0xffffffffu, isw);
            unsigned mc = __ballot_sync(0xffffffffu, isc);
            int basew = 0, basec = 0;
            if (mw) {
                int ldr = __ffs(mw) - 1;
                if (lane == ldr) basew = atomicAdd(s_wcnt, __popc(mw));
                basew = __shfl_sync(0xffffffffu, basew, ldr);
                if (isw) buf[basew + __popc(mw & ((1u << lane) - 1u))] = k;
            }
            if (mc) {
                int ldr = __ffs(mc) - 1;
                if (lane == ldr) basec = atomicAdd(s_ccnt, __popc(mc));
                basec = __shfl_sync(0xffffffffu, basec, ldr);
                if (isc) dstc[basec + __popc(mc & ((1u << lane) - 1u))] = k;
            }
        }
        __syncthreads();
        m = *s_ccnt;
        int w = *s_wcnt;
        if (w + m <= 1024) {
            for (int i = t; i < m; i += 1024) buf[w + i] = dstc[i];
            total = w + m;
            break;
        }
        ull* tmp = src; src = dstc; dstc = tmp;
        __syncthreads();
    }
    __syncthreads();

    // hybrid bitonic sort: element in register, smem for j>=32, shfl for j<=16
    ull v = (t < total) ? buf[t] : ~0ull;
    for (unsigned k = 2; k <= 1024; k <<= 1) {
        unsigned j = k >> 1;
        for (; j >= 32; j >>= 1) {
            buf[t] = v;
            __syncthreads();
            ull c = buf[t ^ j];
            bool keepmin = (((t & k) == 0) == ((t & j) == 0));
            v = keepmin ? (v < c ? v : c) : (v < c ? c : v);
            __syncthreads();
        }
        for (; j > 0; j >>= 1) {
            ull c = __shfl_xor_sync(0xffffffffu, v, j);
            bool keepmin = (((t & k) == 0) == ((t & j) == 0));
            v = keepmin ? (v < c ? v : c) : (v < c ? c : v);
        }
    }

    float* dst = pts_out + (size_t)b * NPTS * 2;
    if (t < NIMP) {
        int n = (int)(v & 0x1FFFull);
        float2 p = og[n];
        dst[t * 2 + 0] = p.x;
        dst[t * 2 + 1] = p.y;
    } else {
        int i = t - NIMP;
        float2 p = ((const float2*)coverage)[(size_t)b * NCOV + i];
        dst[(NIMP + i) * 2 + 0] = p.x;
        dst[(NIMP + i) * 2 + 1] = p.y;
    }
}

// ───────────────────────── k_fused ─────────────────────────
// R10 skeleton EXACTLY (best measured, 76.8 us): 1024 CTAs x 16 points,
// 256 threads, thread tile 4pt x 4col (cg=t&63, pg=t>>6). Paired-x gather
// (LDG.64). w1 staged per-chunk in smem via cp.async (single buffer,
// in-chunk wait), two barriers per chunk, 3 CTAs/SM.
// smem floats: sfb 2*540 | w1s 6912 (reused as part) | w2s 1792 | params 384
#define FU_SFB   0
#define FU_W1S   1080
#define FU_W2S   8248
#define FU_CBL   10040
#define FU_TOT   10424   // floats -> 41696 bytes

#define CHK   27
#define SFS   20        // sfb row stride
#define NTASK (CHK * 16)

__global__ void __launch_bounds__(256, 3) k_fused(
    const float* __restrict__ fine, const float* __restrict__ coarse,
    const float* __restrict__ w1, const float* __restrict__ b1,
    const float* __restrict__ w2, const float* __restrict__ b2,
    const float* __restrict__ pts, float* __restrict__ rend)
{
    extern __shared__ float sm[];
    float*  sfb  = sm + FU_SFB;        // [2][27*20]
    float*  w1s  = sm + FU_W1S;        // [27][256]; reused as part
    float*  w2s  = sm + FU_W2S;        // [256][7]
    int4*   fidx = (int4*)(sm + FU_CBL);          // [16] halved f2 idx
    float4* fpar = (float4*)(sm + FU_CBL + 64);   // [16] (wx, wy, xodd, sel1)
    float4* fmsk = (float4*)(sm + FU_CBL + 128);  // [16] (m00,m01,m10,m11)
    int4*   cidx = (int4*)(sm + FU_CBL + 192);
    float4* cpar = (float4*)(sm + FU_CBL + 256);
    float4* cmsk = (float4*)(sm + FU_CBL + 320);
    float*  part = w1s;                // reused after mainloop

    int t   = threadIdx.x;
    int bp0 = blockIdx.x * 16;
    int b   = bp0 >> 10;
    int cg  = t & 63;               // col group: cols cg*4 .. cg*4+3
    int pg  = t >> 6;               // point group: pts pg*4 .. pg*4+3

    // prologue: per-point params (t<16 fine, 16<=t<32 coarse)
    if (t < 32) {
        int p_ = t & 15;
        int W  = (t < 16) ? FW : CW;
        float2 p = ((const float2*)pts)[bp0 + p_];
        BL o;
        bl_setup(p.x, p.y, W, o);
        int ix0 = o.i00 & (W - 1);
        int ix1 = o.i01 & (W - 1);
        int rb0 = o.i00 - ix0;
        int rb1 = o.i10 - ix0;
        int eb  = ix0 & ~1;
        int c2  = min(eb + 2, W - 2);
        int4  idx = make_int4((rb0 + eb) >> 1, (rb0 + c2) >> 1,
                              (rb1 + eb) >> 1, (rb1 + c2) >> 1);
        float4 par = make_float4(o.wx, o.wy, (float)(ix0 & 1),
                                 (ix1 == ix0 + 1) ? 1.0f : 0.0f);
        float4 msk = make_float4(o.m00, o.m01, o.m10, o.m11);
        if (t < 16) { fidx[p_] = idx; fpar[p_] = par; fmsk[p_] = msk; }
        else        { cidx[p_] = idx; cpar[p_] = par; cmsk[p_] = msk; }
    }
    for (int i = t; i < HID * 7; i += 256) w2s[i] = w2[i];

    // accumulators: 4 pts x 4 cols as 4x2 packed f32x2, init with bias
    ull acc2[4][2];
    {
        ull bv0 = pack2(b1[cg * 4 + 0], b1[cg * 4 + 1]);
        ull bv1 = pack2(b1[cg * 4 + 2], b1[cg * 4 + 3]);
#pragma unroll
        for (int i = 0; i < 4; i++) { acc2[i][0] = bv0; acc2[i][1] = bv1; }
    }
    __syncthreads();

    float2 a0[2], a1[2], b0[2], b1r[2];

    // gather chunk 0 (fine channels 0..26): issue then combine into sfb[0]
#pragma unroll
    for (int s = 0; s < 2; s++) {
        int task = s * 256 + t;
        if (task < NTASK) {
            int kk = task >> 4, p = task & 15;
            const float2* pl2 = (const float2*)(fine + ((size_t)b * FCH + kk) * 65536);
            int4 ix = fidx[p];
            float4 par = fpar[p];
            a0[s] = pl2[ix.x]; a1[s] = pl2[ix.z];
            b0[s] = make_float2(0.f, 0.f); b1r[s] = b0[s];
            if (par.z != 0.0f) { b0[s] = pl2[ix.y]; b1r[s] = pl2[ix.w]; }
        }
    }
#pragma unroll
    for (int s = 0; s < 2; s++) {
        int task = s * 256 + t;
        if (task < NTASK) {
            int kk = task >> 4, p = task & 15;
            float4 par = fpar[p];
            float4 mk  = fmsk[p];
            bool xo = par.z != 0.0f, s1 = par.w != 0.0f;
            float vx00 = xo ? a0[s].y : a0[s].x;
            float t10  = xo ? b0[s].x : a0[s].y;
            float vx10 = s1 ? t10 : vx00;
            float vx01 = xo ? a1[s].y : a1[s].x;
            float t11  = xo ? b1r[s].x : a1[s].y;
            float vx11 = s1 ? t11 : vx01;
            float owx = 1.0f - par.x, owy = 1.0f - par.y;
            sfb[kk * SFS + p] = vx00 * mk.x * (owx * owy) + vx10 * mk.y * (par.x * owy)
                              + vx01 * mk.z * (owx * par.y) + vx11 * mk.w * (par.x * par.y);
        }
    }

    for (int c = 0; c < 5; c++) {
        __syncthreads();   // sfb[c&1] visible; prior compute done -> w1s free
        int k0 = c * CHK;
        // cp.async w1 chunk c (row kk -> w1s[kk*256 + ...])
        for (int i = t; i < CHK * 64; i += 256) {
            int kk = i >> 6, q = i & 63;
            int row = k0 + kk;
            int srow = (row < FCH) ? (CCH + row) : (row - FCH);
            cp_async16(&w1s[kk * 256 + q * 4], w1 + (size_t)srow * HID + q * 4);
        }
        CP_COMMIT();
        // issue paired-x gather LDGs for chunk c+1
        if (c < 4) {
            int k1 = (c + 1) * CHK;
#pragma unroll
            for (int s = 0; s < 2; s++) {
                int task = s * 256 + t;
                if (task < NTASK) {
                    int kk = task >> 4, p = task & 15;
                    int ch = k1 + kk;
                    const float2* pl2;
                    int4 ix; float4 par;
                    if (ch < FCH) {
                        pl2 = (const float2*)(fine + ((size_t)b * FCH + ch) * 65536);
                        ix = fidx[p]; par = fpar[p];
                    } else {
                        pl2 = (const float2*)(coarse + ((size_t)b * CCH + (ch - FCH)) * 4096);
                        ix = cidx[p]; par = cpar[p];
                    }
                    a0[s] = pl2[ix.x]; a1[s] = pl2[ix.z];
                    b0[s] = make_float2(0.f, 0.f); b1r[s] = b0[s];
                    if (par.z != 0.0f) { b0[s] = pl2[ix.y]; b1r[s] = pl2[ix.w]; }
                }
            }
        }
        CP_WAIT0();
        __syncthreads();   // w1s chunk c ready for all threads

        // compute chunk c: 4pt x 4col packed f32x2
        const float* sb = sfb + (c & 1) * (CHK * SFS);
#pragma unroll 3
        for (int kk = 0; kk < CHK; kk++) {
            float4 fv = *(const float4*)&sb[kk * SFS + pg * 4];      // broadcast
            ulonglong2 w = *(const ulonglong2*)&w1s[kk * 256 + cg * 4];
            ull f0 = pack2(fv.x, fv.x);
            ull f1 = pack2(fv.y, fv.y);
            ull f2v = pack2(fv.z, fv.z);
            ull f3 = pack2(fv.w, fv.w);
            acc2[0][0] = fma2(w.x, f0, acc2[0][0]);
            acc2[0][1] = fma2(w.y, f0, acc2[0][1]);
            acc2[1][0] = fma2(w.x, f1, acc2[1][0]);
            acc2[1][1] = fma2(w.y, f1, acc2[1][1]);
            acc2[2][0] = fma2(w.x, f2v, acc2[2][0]);
            acc2[2][1] = fma2(w.y, f2v, acc2[2][1]);
            acc2[3][0] = fma2(w.x, f3, acc2[3][0]);
            acc2[3][1] = fma2(w.y, f3, acc2[3][1]);
        }

        // combine + store gathered chunk c+1 into the other sfb buffer
        if (c < 4) {
            int k1 = (c + 1) * CHK;
            float* so = sfb + ((c + 1) & 1) * (CHK * SFS);
#pragma unroll
            for (int s = 0; s < 2; s++) {
                int task = s * 256 + t;
                if (task < NTASK) {
                    int kk = task >> 4, p = task & 15;
                    int ch = k1 + kk;
                    float4 par, mk;
                    if (ch < FCH) { par = fpar[p]; mk = fmsk[p]; }
                    else          { par = cpar[p]; mk = cmsk[p]; }
                    bool xo = par.z != 0.0f, s1 = par.w != 0.0f;
                    float vx00 = xo ? a0[s].y : a0[s].x;
                    float t10  = xo ? b0[s].x : a0[s].y;
                    float vx10 = s1 ? t10 : vx00;
                    float vx01 = xo ? a1[s].y : a1[s].x;
                    float t11  = xo ? b1r[s].x : a1[s].y;
                    float vx11 = s1 ? t11 : vx01;
                    float owx = 1.0f - par.x, owy = 1.0f - par.y;
                    so[kk * SFS + p] = vx00 * mk.x * (owx * owy) + vx10 * mk.y * (par.x * owy)
                                     + vx01 * mk.z * (owx * par.y) + vx11 * mk.w * (par.x * par.y);
                }
            }
        }
    }
    __syncthreads();   // all compute done; w1s free -> reuse as part

    // epilogue: relu + w2 partials per thread, butterfly over the warp's 32 cgs
    float pr[4][7];
#pragma unroll
    for (int i = 0; i < 4; i++) {
        float h0, h1, h2, h3;
        unpack2(acc2[i][0], h0, h1);
        unpack2(acc2[i][1], h2, h3);
        h0 = fmaxf(h0, 0.0f); h1 = fmaxf(h1, 0.0f);
        h2 = fmaxf(h2, 0.0f); h3 = fmaxf(h3, 0.0f);
        const float* w20 = &w2s[(cg * 4 + 0) * 7];
        const float* w21 = w20 + 7;
        const float* w22 = w20 + 14;
        const float* w23 = w20 + 21;
#pragma unroll
        for (int k = 0; k < 7; k++)
            pr[i][k] = h0 * w20[k] + h1 * w21[k] + h2 * w22[k] + h3 * w23[k];
    }
#pragma unroll
    for (int off = 16; off > 0; off >>= 1) {
#pragma unroll
        for (int i = 0; i < 4; i++)
#pragma unroll
            for (int k = 0; k < 7; k++)
                pr[i][k] += __shfl_xor_sync(0xffffffffu, pr[i][k], off);
    }
    int wrp = t >> 5;   // warps {2w, 2w+1} share pg=w, cover cgs 0-31 / 32-63
    if ((t & 31) == 0) {
#pragma unroll
        for (int i = 0; i < 4; i++)
#pragma unroll
            for (int k = 0; k < 7; k++)
                part[((wrp & 1) * 16 + (pg * 4 + i)) * 7 + k] = pr[i][k];
    }
    __syncthreads();

    // final: add the two warp-halves + b2, write rend[b][k][p]
    if (t < 16 * 7) {
        int p = t / 7, k = t % 7;
        float s = b2[k] + part[p * 7 + k] + part[(16 + p) * 7 + k];
        rend[((size_t)b * CCH + k) * NPTS + (bp0 & 1023) + p] = s;
    }
}

extern "C" void kernel_launch(void* const* d_in, const int* in_sizes, int n_in,
                              void* d_out, int out_size) {
    (void)in_sizes; (void)n_in; (void)out_size;
    const float* fine     = (const float*)d_in[0];
    const float* coarse   = (const float*)d_in[1];
    const float* w1       = (const float*)d_in[2];
    const float* b1       = (const float*)d_in[3];
    const float* w2       = (const float*)d_in[4];
    const float* b2       = (const float*)d_in[5];
    const float* over_gen = (const float*)d_in[6];
    const float* coverage = (const float*)d_in[7];

    float* rend = (float*)d_out;                 // [16][7][1024]
    float* pts  = rend + NB * CCH * NPTS;        // [16][1024][2]

    cudaFuncSetAttribute(k_prep,  cudaFuncAttributeMaxDynamicSharedMemorySize, PR_SMEM);
    cudaFuncSetAttribute(k_fused, cudaFuncAttributeMaxDynamicSharedMemorySize, FU_TOT * 4);

    k_prep<<<NB, 1024, PR_SMEM>>>(coarse, over_gen, coverage, pts);
    k_fused<<<NB * NPTS / 16, 256, FU_TOT * 4>>>(fine, coarse, w1, b1, w2, b2, pts, rend);
}